// round 16
// baseline (speedup 1.0000x reference)
#include <cuda_runtime.h>
#include <cuda_fp16.h>

#define N_MAX 100000
#define D 128
// Normalized rows in fp16: 100000 x 128 x 2B = 25.6 MB (L2-resident).
__device__ __half g_xh[N_MAX * D];

// Kernel 1: one warp per row. fp32 norm, write fp16 row. Streaming read of x
// (evict-first) keeps L2 free for g_xh, which the edge kernel re-reads.
// 512-thread blocks (16 rows/block) to minimize block churn.
__global__ void normalize_kernel(const float* __restrict__ x, int n) {
    int warp = (blockIdx.x * blockDim.x + threadIdx.x) >> 5;
    int lane = threadIdx.x & 31;
    if (warp >= n) return;
    const float4* row = reinterpret_cast<const float4*>(x + (size_t)warp * D);
    float4 v = __ldcs(row + lane);
    float ss = v.x * v.x + v.y * v.y + v.z * v.z + v.w * v.w;
#pragma unroll
    for (int o = 16; o; o >>= 1) ss += __shfl_xor_sync(0xffffffffu, ss, o);
    float r = 1.0f / fmaxf(sqrtf(ss), 1e-12f);
    __half2 h0 = __floats2half2_rn(v.x * r, v.y * r);
    __half2 h1 = __floats2half2_rn(v.z * r, v.w * r);
    uint2 packed;
    packed.x = *reinterpret_cast<unsigned*>(&h0);
    packed.y = *reinterpret_cast<unsigned*>(&h1);
    reinterpret_cast<uint2*>(g_xh + (size_t)warp * D)[lane] = packed;
}

// Kernel 2: one warp = 8 edges, one-shot (cross-warp MLP hides latency).
// 128-thread blocks: finer residency quantization. Lanes 0..15 load 16
// indices pre-scaled to byte offsets; shfl broadcast. Each LDG.128 gathers
// TWO rows (16 lanes x 16B per row): 8 gathers/warp. half2 math, early fp32
// conversion, value-packing butterfly (8 SHFL for all 8 edges).
// Converged at the LTS chip bandwidth cap (~335 MB @ ~13 TB/s).
__global__ void __launch_bounds__(128, 12)
edge_dot_kernel(const int* __restrict__ src,
                const int* __restrict__ dst,
                float* __restrict__ out, int e, int n) {
    int warp = (blockIdx.x * blockDim.x + threadIdx.x) >> 5;
    int lane = threadIdx.x & 31;
    int e0 = warp * 8;
    if (e0 >= e) return;
    bool full = (e0 + 8 <= e);   // uniform per warp; E%8==0 -> always true

    // lanes 0..7 -> src[e0+lane], lanes 8..15 -> dst[e0+lane-8].
    unsigned myoff = 0;
    if (lane < 16) {
        int k = e0 + (lane & 7);
        if (full || k < e) {
            int idx = (lane < 8) ? __ldg(src + k) : __ldg(dst + k);
            myoff = (unsigned)idx << 8;   // row * 256 bytes
        }
    }

    const int laneHi = lane >> 4;    // 0: even edges, 1: odd edges
    const unsigned laneOff = (unsigned)(lane & 15) * 16u;
    const char* base = reinterpret_cast<const char*>(g_xh);

    unsigned so[4], dofs[4];
#pragma unroll
    for (int k = 0; k < 4; k++) {
        so[k]   = __shfl_sync(0xffffffffu, myoff, 2 * k + laneHi) + laneOff;
        dofs[k] = __shfl_sync(0xffffffffu, myoff, 8 + 2 * k + laneHi) + laneOff;
    }

    uint4 a[4], b[4];
#pragma unroll
    for (int k = 0; k < 4; k++)
        a[k] = __ldg(reinterpret_cast<const uint4*>(base + so[k]));
#pragma unroll
    for (int k = 0; k < 4; k++)
        b[k] = __ldg(reinterpret_cast<const uint4*>(base + dofs[k]));

    float acc[4];
#pragma unroll
    for (int k = 0; k < 4; k++) {
        __half2 a0 = *reinterpret_cast<__half2*>(&a[k].x);
        __half2 a1 = *reinterpret_cast<__half2*>(&a[k].y);
        __half2 a2 = *reinterpret_cast<__half2*>(&a[k].z);
        __half2 a3 = *reinterpret_cast<__half2*>(&a[k].w);
        __half2 b0 = *reinterpret_cast<__half2*>(&b[k].x);
        __half2 b1 = *reinterpret_cast<__half2*>(&b[k].y);
        __half2 b2 = *reinterpret_cast<__half2*>(&b[k].z);
        __half2 b3 = *reinterpret_cast<__half2*>(&b[k].w);
        __half2 g0 = __hfma2(a1, b1, __hmul2(a0, b0));
        __half2 g1 = __hfma2(a3, b3, __hmul2(a2, b2));
        float2 f0 = __half22float2(g0);
        float2 f1 = __half22float2(g1);
        acc[k] = (f0.x + f0.y) + (f1.x + f1.y);
    }

    // Value-packing butterfly within 16-lane halves.
#pragma unroll
    for (int k = 0; k < 4; k++)
        acc[k] += __shfl_xor_sync(0xffffffffu, acc[k], 8);
    float m0 = (lane & 8) ? acc[1] : acc[0];
    float m1 = (lane & 8) ? acc[3] : acc[2];
    m0 += __shfl_xor_sync(0xffffffffu, m0, 4);
    m1 += __shfl_xor_sync(0xffffffffu, m1, 4);
    float q = (lane & 4) ? m1 : m0;
    q += __shfl_xor_sync(0xffffffffu, q, 2);
    q += __shfl_xor_sync(0xffffffffu, q, 1);

    if ((lane & 3) == 0) {
        int k = ((lane >> 3) & 1) + ((lane & 4) ? 2 : 0);
        int eidx = e0 + 2 * k + laneHi;
        if (full || eidx < e) out[eidx] = q;
    }
}

extern "C" void kernel_launch(void* const* d_in, const int* in_sizes, int n_in,
                              void* d_out, int out_size) {
    const float* x   = (const float*)d_in[0];
    const int*   src = (const int*)d_in[1];
    const int*   dst = (const int*)d_in[2];
    float*       out = (float*)d_out;

    int n = in_sizes[0] / D;   // 100000
    int e = in_sizes[1];       // 640000

    int nblk1 = (n + 15) / 16;               // 16 warps/block (512 threads)
    normalize_kernel<<<nblk1, 512>>>(x, n);

    int warps = (e + 7) / 8;
    int nblk2 = (warps + 3) / 4;             // one-shot: 20000 blocks x 4 warps
    edge_dot_kernel<<<nblk2, 128>>>(src, dst, out, e, n);
}

// round 17
// speedup vs baseline: 1.0474x; 1.0474x over previous
#include <cuda_runtime.h>
#include <cuda_fp16.h>

#define N_MAX 100000
#define D 128
// Normalized rows in fp16: 100000 x 128 x 2B = 25.6 MB (L2-resident).
__device__ __half g_xh[N_MAX * D];

// Kernel 1: one warp per row. fp32 norm, write fp16 row. Streaming read of x
// (evict-first) keeps L2 free for g_xh, which the edge kernel re-reads.
__global__ void normalize_kernel(const float* __restrict__ x, int n) {
    int warp = (blockIdx.x * blockDim.x + threadIdx.x) >> 5;
    int lane = threadIdx.x & 31;
    if (warp >= n) return;
    const float4* row = reinterpret_cast<const float4*>(x + (size_t)warp * D);
    float4 v = __ldcs(row + lane);
    float ss = v.x * v.x + v.y * v.y + v.z * v.z + v.w * v.w;
#pragma unroll
    for (int o = 16; o; o >>= 1) ss += __shfl_xor_sync(0xffffffffu, ss, o);
    float r = 1.0f / fmaxf(sqrtf(ss), 1e-12f);
    __half2 h0 = __floats2half2_rn(v.x * r, v.y * r);
    __half2 h1 = __floats2half2_rn(v.z * r, v.w * r);
    uint2 packed;
    packed.x = *reinterpret_cast<unsigned*>(&h0);
    packed.y = *reinterpret_cast<unsigned*>(&h1);
    reinterpret_cast<uint2*>(g_xh + (size_t)warp * D)[lane] = packed;
}

// Kernel 2: one warp = 8 edges, one-shot (cross-warp MLP hides latency).
// 128-thread blocks: finer residency quantization. Lanes 0..15 load 16
// indices pre-scaled to byte offsets; shfl broadcast. Each LDG.128 gathers
// TWO rows (16 lanes x 16B per row): 8 gathers/warp. half2 math, early fp32
// conversion, value-packing butterfly (8 SHFL for all 8 edges).
// Converged at the LTS chip bandwidth cap (~335 MB @ ~13 TB/s).
__global__ void __launch_bounds__(128, 12)
edge_dot_kernel(const int* __restrict__ src,
                const int* __restrict__ dst,
                float* __restrict__ out, int e, int n) {
    int warp = (blockIdx.x * blockDim.x + threadIdx.x) >> 5;
    int lane = threadIdx.x & 31;
    int e0 = warp * 8;
    if (e0 >= e) return;
    bool full = (e0 + 8 <= e);   // uniform per warp; E%8==0 -> always true

    // lanes 0..7 -> src[e0+lane], lanes 8..15 -> dst[e0+lane-8].
    unsigned myoff = 0;
    if (lane < 16) {
        int k = e0 + (lane & 7);
        if (full || k < e) {
            int idx = (lane < 8) ? __ldg(src + k) : __ldg(dst + k);
            myoff = (unsigned)idx << 8;   // row * 256 bytes
        }
    }

    const int laneHi = lane >> 4;    // 0: even edges, 1: odd edges
    const unsigned laneOff = (unsigned)(lane & 15) * 16u;
    const char* base = reinterpret_cast<const char*>(g_xh);

    unsigned so[4], dofs[4];
#pragma unroll
    for (int k = 0; k < 4; k++) {
        so[k]   = __shfl_sync(0xffffffffu, myoff, 2 * k + laneHi) + laneOff;
        dofs[k] = __shfl_sync(0xffffffffu, myoff, 8 + 2 * k + laneHi) + laneOff;
    }

    uint4 a[4], b[4];
#pragma unroll
    for (int k = 0; k < 4; k++)
        a[k] = __ldg(reinterpret_cast<const uint4*>(base + so[k]));
#pragma unroll
    for (int k = 0; k < 4; k++)
        b[k] = __ldg(reinterpret_cast<const uint4*>(base + dofs[k]));

    float acc[4];
#pragma unroll
    for (int k = 0; k < 4; k++) {
        __half2 a0 = *reinterpret_cast<__half2*>(&a[k].x);
        __half2 a1 = *reinterpret_cast<__half2*>(&a[k].y);
        __half2 a2 = *reinterpret_cast<__half2*>(&a[k].z);
        __half2 a3 = *reinterpret_cast<__half2*>(&a[k].w);
        __half2 b0 = *reinterpret_cast<__half2*>(&b[k].x);
        __half2 b1 = *reinterpret_cast<__half2*>(&b[k].y);
        __half2 b2 = *reinterpret_cast<__half2*>(&b[k].z);
        __half2 b3 = *reinterpret_cast<__half2*>(&b[k].w);
        __half2 g0 = __hfma2(a1, b1, __hmul2(a0, b0));
        __half2 g1 = __hfma2(a3, b3, __hmul2(a2, b2));
        float2 f0 = __half22float2(g0);
        float2 f1 = __half22float2(g1);
        acc[k] = (f0.x + f0.y) + (f1.x + f1.y);
    }

    // Value-packing butterfly within 16-lane halves.
#pragma unroll
    for (int k = 0; k < 4; k++)
        acc[k] += __shfl_xor_sync(0xffffffffu, acc[k], 8);
    float m0 = (lane & 8) ? acc[1] : acc[0];
    float m1 = (lane & 8) ? acc[3] : acc[2];
    m0 += __shfl_xor_sync(0xffffffffu, m0, 4);
    m1 += __shfl_xor_sync(0xffffffffu, m1, 4);
    float q = (lane & 4) ? m1 : m0;
    q += __shfl_xor_sync(0xffffffffu, q, 2);
    q += __shfl_xor_sync(0xffffffffu, q, 1);

    if ((lane & 3) == 0) {
        int k = ((lane >> 3) & 1) + ((lane & 4) ? 2 : 0);
        int eidx = e0 + 2 * k + laneHi;
        if (full || eidx < e) out[eidx] = q;
    }
}

extern "C" void kernel_launch(void* const* d_in, const int* in_sizes, int n_in,
                              void* d_out, int out_size) {
    const float* x   = (const float*)d_in[0];
    const int*   src = (const int*)d_in[1];
    const int*   dst = (const int*)d_in[2];
    float*       out = (float*)d_out;

    int n = in_sizes[0] / D;   // 100000
    int e = in_sizes[1];       // 640000

    int nblk1 = (n + 7) / 8;                 // 8 warps/block (256 threads)
    normalize_kernel<<<nblk1, 256>>>(x, n);

    int warps = (e + 7) / 8;
    int nblk2 = (warps + 3) / 4;             // one-shot: 20000 blocks x 4 warps
    edge_dot_kernel<<<nblk2, 128>>>(src, dst, out, e, n);
}